// round 3
// baseline (speedup 1.0000x reference)
#include <cuda_runtime.h>
#include <cuda_bf16.h>
#include <cstdint>

// ============================================================================
// DigitConvolutionalModel: conv folds into W1 -> pure 4-layer MLP
//   784 -> 200 -> 200 -> 200 -> 10, batch 65536, fp32 in/out.
// Strategy: fused tensor-core kernel, bf16x3 split arithmetic (fp32-accurate),
//   mma.sync.m16n8k16. One CTA = 128 rows; 8 warps = 4 M-quarters x 2 N-halves.
//   Activations live in SMEM as pre-split bf16 hi/lo (conflict-free stride).
//   Weights pre-folded + pre-split + fragment-linearized by a prep kernel,
//   streamed per-k16-chunk with double-buffered cp.async.
// ============================================================================

#define CTA_THREADS 256

// padded dims: K1=784 (49 k-chunks), HID pad 208 (13 k-chunks, 26 n8-tiles),
// OUT pad 16 (2 n8-tiles)
#define NK1 49
#define NKH 13
#define NJH 26
#define NJO 2

// fragment-linear weight scratch (uint4 per (ks, j, lane)):
// {b0_hi, b1_hi, b0_lo, b1_lo}, each = 2 packed bf16 (low 16 bits = even k)
__device__ uint4 g_Wb1[NK1 * NJH * 32];   // 40768
__device__ uint4 g_Wb2[NKH * NJH * 32];   // 10816
__device__ uint4 g_Wb3[NKH * NJH * 32];   // 10816
__device__ uint4 g_Wb4[NKH * NJO * 32];   //   832

// ---------------------------------------------------------------------------
// helpers
// ---------------------------------------------------------------------------
__device__ __forceinline__ void split_pack(float x, float y, uint32_t& h, uint32_t& l) {
    __nv_bfloat16 hx = __float2bfloat16_rn(x);
    __nv_bfloat16 hy = __float2bfloat16_rn(y);
    float rx = x - __bfloat162float(hx);
    float ry = y - __bfloat162float(hy);
    __nv_bfloat162 H; H.x = hx; H.y = hy;
    __nv_bfloat162 L; L.x = __float2bfloat16_rn(rx); L.y = __float2bfloat16_rn(ry);
    h = *reinterpret_cast<uint32_t*>(&H);
    l = *reinterpret_cast<uint32_t*>(&L);
}

__device__ __forceinline__ void mma_bf16(float* c, const uint32_t* a,
                                         uint32_t b0, uint32_t b1) {
    asm volatile(
        "mma.sync.aligned.m16n8k16.row.col.f32.bf16.bf16.f32 "
        "{%0,%1,%2,%3},{%4,%5,%6,%7},{%8,%9},{%0,%1,%2,%3};"
        : "+f"(c[0]), "+f"(c[1]), "+f"(c[2]), "+f"(c[3])
        : "r"(a[0]), "r"(a[1]), "r"(a[2]), "r"(a[3]), "r"(b0), "r"(b1));
}

__device__ __forceinline__ void cp16(void* dst_smem, const void* src) {
    uint32_t d = (uint32_t)__cvta_generic_to_shared(dst_smem);
    asm volatile("cp.async.cg.shared.global [%0], [%1], 16;" :: "r"(d), "l"(src));
}
#define CP_COMMIT asm volatile("cp.async.commit_group;" ::: "memory")
#define CP_WAIT1  asm volatile("cp.async.wait_group 1;" ::: "memory")

// ---------------------------------------------------------------------------
// prep kernel: fold conv into W1eff, bf16 hi/lo split, fragment-linearize
// ---------------------------------------------------------------------------
__device__ __forceinline__ float w_l1(const float* cw, const float* W1, int k, int n) {
    if (n >= 200) return 0.f;
    int r = k / 28, c = k % 28;
    float s = 0.f;
    #pragma unroll
    for (int dy = 0; dy < 3; ++dy) {
        int i = r - dy;
        if (i < 0 || i > 25) continue;
        #pragma unroll
        for (int dx = 0; dx < 3; ++dx) {
            int j = c - dx;
            if (j < 0 || j > 25) continue;
            s += cw[dy * 3 + dx] * W1[(i * 26 + j) * 200 + n];
        }
    }
    return s;
}

__global__ void prep_kernel(const float* __restrict__ cw,
                            const float* __restrict__ W1,
                            const float* __restrict__ W2,
                            const float* __restrict__ W3,
                            const float* __restrict__ W4) {
    int s = blockIdx.x * CTA_THREADS + threadIdx.x;
    const int E1 = NK1 * NJH * 32;
    const int E2 = E1 + NKH * NJH * 32;
    const int E3 = E2 + NKH * NJH * 32;
    const int E4 = E3 + NKH * NJO * 32;
    if (s >= E4) return;

    uint4* dst; int loc, nj, which;
    if (s < E1)      { dst = g_Wb1; loc = s;      nj = NJH; which = 1; }
    else if (s < E2) { dst = g_Wb2; loc = s - E1; nj = NJH; which = 2; }
    else if (s < E3) { dst = g_Wb3; loc = s - E2; nj = NJH; which = 3; }
    else             { dst = g_Wb4; loc = s - E3; nj = NJO; which = 4; }

    int lane = loc & 31;
    int j    = (loc >> 5) % nj;
    int ks   = loc / (nj * 32);
    int g = lane >> 2, t = lane & 3;
    int n  = 8 * j + g;
    int k0 = 16 * ks + 2 * t;

    float w0, w1, w8, w9;
    if (which == 1) {
        w0 = w_l1(cw, W1, k0,     n);
        w1 = w_l1(cw, W1, k0 + 1, n);
        w8 = w_l1(cw, W1, k0 + 8, n);
        w9 = w_l1(cw, W1, k0 + 9, n);
    } else if (which == 4) {
        w0 = (k0     < 200 && n < 10) ? W4[(k0)     * 10 + n] : 0.f;
        w1 = (k0 + 1 < 200 && n < 10) ? W4[(k0 + 1) * 10 + n] : 0.f;
        w8 = (k0 + 8 < 200 && n < 10) ? W4[(k0 + 8) * 10 + n] : 0.f;
        w9 = (k0 + 9 < 200 && n < 10) ? W4[(k0 + 9) * 10 + n] : 0.f;
    } else {
        const float* W = (which == 2) ? W2 : W3;
        w0 = (k0     < 200 && n < 200) ? W[(k0)     * 200 + n] : 0.f;
        w1 = (k0 + 1 < 200 && n < 200) ? W[(k0 + 1) * 200 + n] : 0.f;
        w8 = (k0 + 8 < 200 && n < 200) ? W[(k0 + 8) * 200 + n] : 0.f;
        w9 = (k0 + 9 < 200 && n < 200) ? W[(k0 + 9) * 200 + n] : 0.f;
    }

    uint32_t b0h, b0l, b1h, b1l;
    split_pack(w0, w1, b0h, b0l);
    split_pack(w8, w9, b1h, b1l);
    dst[loc] = make_uint4(b0h, b1h, b0l, b1l);
}

// ---------------------------------------------------------------------------
// main fused kernel
// SMEM (floats):
//   [0,5120)        xs: 2 x [128][20] fp32 x-stage (stride 20)
//   [5120,11776)    ws: 2 x [832] uint4 weight stage
//   [11776,25600)   h_hi: [128][216] bf16 (as 128*108 u32, stride 108 u32)
//   [25600,39424)   h_lo: same
//   [39424,40064)   sb: biases b1[208] b2[208] b3[208] b4[16]
// ---------------------------------------------------------------------------
#define SMEM_BYTES 160256

__global__ void __launch_bounds__(CTA_THREADS, 1)
mlp_kernel(const float* __restrict__ x,
           const float* __restrict__ b1, const float* __restrict__ b2,
           const float* __restrict__ b3, const float* __restrict__ b4,
           float* __restrict__ out) {
    extern __shared__ float smf[];
    float*    xs = smf;                               // 2 x 2560 floats
    uint4*    ws = (uint4*)(smf + 5120);              // 2 x 832 uint4
    uint32_t* hh = (uint32_t*)(smf + 11776);          // 128*108 u32
    uint32_t* hl = (uint32_t*)(smf + 25600);
    float*    sb = smf + 39424;

    const int tid  = threadIdx.x;
    const int lane = tid & 31;
    const int warp = tid >> 5;
    const int g = lane >> 2, t = lane & 3;
    const int mq = warp >> 1;       // M-quarter 0..3 (32 rows each)
    const int nh = warp & 1;        // N-half
    const int r0 = blockIdx.x * 128;

    // biases (padded)
    if (tid < 208) {
        sb[tid]       = (tid < 200) ? b1[tid] : 0.f;
        sb[208 + tid] = (tid < 200) ? b2[tid] : 0.f;
        sb[416 + tid] = (tid < 200) ? b3[tid] : 0.f;
    }
    if (tid < 16) sb[624 + tid] = (tid < 10) ? b4[tid] : 0.f;

    float C[2][13][4];

    // --------------------- helper lambdas ---------------------
    auto stage_w = [&](const uint4* src, int count, int buf) {
        uint4* d = ws + buf * 832;
        for (int i = tid; i < count; i += CTA_THREADS) cp16(d + i, src + i);
    };
    auto stage_x = [&](int ks, int buf) {
        float* d = xs + buf * 2560;
        for (int i = tid; i < 512; i += CTA_THREADS) {
            int row = i >> 2, seg = i & 3;
            cp16(d + row * 20 + seg * 4, x + (size_t)(r0 + row) * 784 + ks * 16 + seg * 4);
        }
    };
    auto zeroC = [&]() {
        #pragma unroll
        for (int mt = 0; mt < 2; ++mt)
            #pragma unroll
            for (int j = 0; j < 13; ++j)
                #pragma unroll
                for (int q = 0; q < 4; ++q) C[mt][j][q] = 0.f;
    };
    auto store_h = [&](const float* bias) {
        #pragma unroll
        for (int mt = 0; mt < 2; ++mt) {
            int row = mq * 32 + mt * 16 + g;
            #pragma unroll
            for (int j = 0; j < 13; ++j) {
                int J = 13 * nh + j;
                float2 bb = *(const float2*)(bias + 8 * J + 2 * t);
                float v0 = fmaxf(C[mt][j][0] + bb.x, 0.f);
                float v1 = fmaxf(C[mt][j][1] + bb.y, 0.f);
                float v2 = fmaxf(C[mt][j][2] + bb.x, 0.f);
                float v3 = fmaxf(C[mt][j][3] + bb.y, 0.f);
                uint32_t H, L;
                split_pack(v0, v1, H, L);
                hh[row * 108 + 4 * J + t] = H;
                hl[row * 108 + 4 * J + t] = L;
                split_pack(v2, v3, H, L);
                hh[(row + 8) * 108 + 4 * J + t] = H;
                hl[(row + 8) * 108 + 4 * J + t] = L;
            }
        }
    };
    auto load_a_h = [&](int ks, uint32_t ah[2][4], uint32_t al[2][4]) {
        #pragma unroll
        for (int mt = 0; mt < 2; ++mt) {
            int base = (mq * 32 + mt * 16 + g) * 108 + 8 * ks + t;
            ah[mt][0] = hh[base];
            ah[mt][1] = hh[base + 8 * 108];
            ah[mt][2] = hh[base + 4];
            ah[mt][3] = hh[base + 4 + 8 * 108];
            al[mt][0] = hl[base];
            al[mt][1] = hl[base + 8 * 108];
            al[mt][2] = hl[base + 4];
            al[mt][3] = hl[base + 4 + 8 * 108];
        }
    };

    // =========================== Layer 1 (K=784) ===========================
    zeroC();
    stage_x(0, 0);
    stage_w(g_Wb1, 832, 0);
    CP_COMMIT;
    for (int ks = 0; ks < NK1; ++ks) {
        __syncthreads();                       // prior buf consumption done
        int cur = ks & 1, nb = cur ^ 1;
        if (ks + 1 < NK1) { stage_x(ks + 1, nb); stage_w(g_Wb1 + (ks + 1) * 832, 832, nb); }
        CP_COMMIT; CP_WAIT1;
        __syncthreads();                       // cur buffers visible

        uint32_t ah[2][4], al[2][4];
        #pragma unroll
        for (int mt = 0; mt < 2; ++mt) {
            const float* xb = xs + cur * 2560 + (mq * 32 + mt * 16 + g) * 20;
            float2 p0 = *(const float2*)(xb + 2 * t);
            float2 p1 = *(const float2*)(xb + 160 + 2 * t);        // row+8
            float2 p2 = *(const float2*)(xb + 2 * t + 8);          // k+8
            float2 p3 = *(const float2*)(xb + 160 + 2 * t + 8);
            split_pack(p0.x, p0.y, ah[mt][0], al[mt][0]);
            split_pack(p1.x, p1.y, ah[mt][1], al[mt][1]);
            split_pack(p2.x, p2.y, ah[mt][2], al[mt][2]);
            split_pack(p3.x, p3.y, ah[mt][3], al[mt][3]);
        }
        const uint4* wb = ws + cur * 832 + nh * 13 * 32 + lane;
        #pragma unroll
        for (int j = 0; j < 13; ++j) {
            uint4 w = wb[j * 32];
            #pragma unroll
            for (int mt = 0; mt < 2; ++mt) {
                mma_bf16(C[mt][j], ah[mt], w.x, w.y);   // hi*hi
                mma_bf16(C[mt][j], al[mt], w.x, w.y);   // lo*hi
                mma_bf16(C[mt][j], ah[mt], w.z, w.w);   // hi*lo
            }
        }
    }
    __syncthreads();
    store_h(sb);
    __syncthreads();

    // ======================= Layers 2 & 3 (K=208) ==========================
    const uint4* Wmid[2] = { g_Wb2, g_Wb3 };
    for (int l = 0; l < 2; ++l) {
        zeroC();
        stage_w(Wmid[l], 832, 0);
        CP_COMMIT;
        for (int ks = 0; ks < NKH; ++ks) {
            __syncthreads();
            int cur = ks & 1, nb = cur ^ 1;
            if (ks + 1 < NKH) stage_w(Wmid[l] + (ks + 1) * 832, 832, nb);
            CP_COMMIT; CP_WAIT1;
            __syncthreads();

            uint32_t ah[2][4], al[2][4];
            load_a_h(ks, ah, al);
            const uint4* wb = ws + cur * 832 + nh * 13 * 32 + lane;
            #pragma unroll
            for (int j = 0; j < 13; ++j) {
                uint4 w = wb[j * 32];
                #pragma unroll
                for (int mt = 0; mt < 2; ++mt) {
                    mma_bf16(C[mt][j], ah[mt], w.x, w.y);
                    mma_bf16(C[mt][j], al[mt], w.x, w.y);
                    mma_bf16(C[mt][j], ah[mt], w.z, w.w);
                }
            }
        }
        __syncthreads();                 // all h reads done before overwrite
        store_h(sb + 208 * (l + 1));
        __syncthreads();
    }

    // =========================== Layer 4 (N=10) ============================
    float C4[2][4];
    #pragma unroll
    for (int mt = 0; mt < 2; ++mt)
        #pragma unroll
        for (int q = 0; q < 4; ++q) C4[mt][q] = 0.f;

    stage_w(g_Wb4, 64, 0);
    CP_COMMIT;
    for (int ks = 0; ks < NKH; ++ks) {
        __syncthreads();
        int cur = ks & 1, nb = cur ^ 1;
        if (ks + 1 < NKH) stage_w(g_Wb4 + (ks + 1) * 64, 64, nb);
        CP_COMMIT; CP_WAIT1;
        __syncthreads();

        uint32_t ah[2][4], al[2][4];
        load_a_h(ks, ah, al);
        uint4 w = ws[cur * 832 + nh * 32 + lane];
        #pragma unroll
        for (int mt = 0; mt < 2; ++mt) {
            mma_bf16(C4[mt], ah[mt], w.x, w.y);
            mma_bf16(C4[mt], al[mt], w.x, w.y);
            mma_bf16(C4[mt], ah[mt], w.z, w.w);
        }
    }

    // output: cols 0..9 (tile nh*8 + 2t; guard padded cols)
    if (nh == 0 || t == 0) {
        int col = 8 * nh + 2 * t;
        float2 bb = *(const float2*)(sb + 624 + col);
        #pragma unroll
        for (int mt = 0; mt < 2; ++mt) {
            int rowg = r0 + mq * 32 + mt * 16 + g;
            float2 o0 = { C4[mt][0] + bb.x, C4[mt][1] + bb.y };
            float2 o1 = { C4[mt][2] + bb.x, C4[mt][3] + bb.y };
            *(float2*)(out + (size_t)rowg * 10 + col)       = o0;
            *(float2*)(out + (size_t)(rowg + 8) * 10 + col) = o1;
        }
    }
}

// ---------------------------------------------------------------------------
extern "C" void kernel_launch(void* const* d_in, const int* in_sizes, int n_in,
                              void* d_out, int out_size) {
    const float* x  = (const float*)d_in[0];
    const float* cw = (const float*)d_in[1];
    const float* W1 = (const float*)d_in[2];
    const float* b1 = (const float*)d_in[3];
    const float* W2 = (const float*)d_in[4];
    const float* b2 = (const float*)d_in[5];
    const float* W3 = (const float*)d_in[6];
    const float* b3 = (const float*)d_in[7];
    const float* W4 = (const float*)d_in[8];
    const float* b4 = (const float*)d_in[9];
    float* out = (float*)d_out;

    cudaFuncSetAttribute(mlp_kernel, cudaFuncAttributeMaxDynamicSharedMemorySize, SMEM_BYTES);

    prep_kernel<<<247, CTA_THREADS>>>(cw, W1, W2, W3, W4);
    mlp_kernel<<<512, CTA_THREADS, SMEM_BYTES>>>(x, b1, b2, b3, b4, out);
}

// round 6
// speedup vs baseline: 1.2311x; 1.2311x over previous
#include <cuda_runtime.h>
#include <cuda_bf16.h>
#include <cstdint>

// ============================================================================
// DigitConvolutionalModel: conv folds into W1 -> pure 4-layer MLP
//   784 -> 200 -> 200 -> 200 -> 10, batch 65536, fp32 in/out.
// Legacy-tensor path (toolchain targets sm_100: no tcgen05).
//   bf16x3 split arithmetic (fp32-accurate), mma.sync.m16n8k16.
//   One CTA = 64 rows, 256 threads, 8 warps = 4 M-quarters(16 rows) x 2 N-halves.
//   SMEM 94.7 KB -> 2 CTAs/SM so barrier/staging stalls overlap across CTAs.
//   Weights pre-folded + pre-split + fragment-linearized by a prep kernel,
//   streamed per-k16-chunk with double-buffered cp.async.
// ============================================================================

#define CTA_THREADS 256

// padded dims: K1=784 (49 k-chunks), HID pad 208 (13 k-chunks, 26 n8-tiles),
// OUT pad 16 (2 n8-tiles)
#define NK1 49
#define NKH 13
#define NJH 26
#define NJO 2

// fragment-linear weight scratch (uint4 per (ks, j, lane)):
// {b0_hi, b1_hi, b0_lo, b1_lo}, each = 2 packed bf16 (low 16 bits = even k)
__device__ uint4 g_Wb1[NK1 * NJH * 32];   // 40768
__device__ uint4 g_Wb2[NKH * NJH * 32];   // 10816
__device__ uint4 g_Wb3[NKH * NJH * 32];   // 10816
__device__ uint4 g_Wb4[NKH * NJO * 32];   //   832

// ---------------------------------------------------------------------------
// helpers
// ---------------------------------------------------------------------------
__device__ __forceinline__ void split_pack(float x, float y, uint32_t& h, uint32_t& l) {
    __nv_bfloat16 hx = __float2bfloat16_rn(x);
    __nv_bfloat16 hy = __float2bfloat16_rn(y);
    float rx = x - __bfloat162float(hx);
    float ry = y - __bfloat162float(hy);
    __nv_bfloat162 H; H.x = hx; H.y = hy;
    __nv_bfloat162 L; L.x = __float2bfloat16_rn(rx); L.y = __float2bfloat16_rn(ry);
    h = *reinterpret_cast<uint32_t*>(&H);
    l = *reinterpret_cast<uint32_t*>(&L);
}

__device__ __forceinline__ void mma_bf16(float* c, const uint32_t* a,
                                         uint32_t b0, uint32_t b1) {
    asm volatile(
        "mma.sync.aligned.m16n8k16.row.col.f32.bf16.bf16.f32 "
        "{%0,%1,%2,%3},{%4,%5,%6,%7},{%8,%9},{%0,%1,%2,%3};"
        : "+f"(c[0]), "+f"(c[1]), "+f"(c[2]), "+f"(c[3])
        : "r"(a[0]), "r"(a[1]), "r"(a[2]), "r"(a[3]), "r"(b0), "r"(b1));
}

__device__ __forceinline__ void cp16(void* dst_smem, const void* src) {
    uint32_t d = (uint32_t)__cvta_generic_to_shared(dst_smem);
    asm volatile("cp.async.cg.shared.global [%0], [%1], 16;" :: "r"(d), "l"(src));
}
#define CP_COMMIT asm volatile("cp.async.commit_group;" ::: "memory")
#define CP_WAIT1  asm volatile("cp.async.wait_group 1;" ::: "memory")

// ---------------------------------------------------------------------------
// prep kernel: fold conv into W1eff, bf16 hi/lo split, fragment-linearize
// ---------------------------------------------------------------------------
__device__ __forceinline__ float w_l1(const float* cw, const float* W1, int k, int n) {
    if (n >= 200) return 0.f;
    int r = k / 28, c = k % 28;
    float s = 0.f;
    #pragma unroll
    for (int dy = 0; dy < 3; ++dy) {
        int i = r - dy;
        if (i < 0 || i > 25) continue;
        #pragma unroll
        for (int dx = 0; dx < 3; ++dx) {
            int j = c - dx;
            if (j < 0 || j > 25) continue;
            s += cw[dy * 3 + dx] * W1[(i * 26 + j) * 200 + n];
        }
    }
    return s;
}

__global__ void prep_kernel(const float* __restrict__ cw,
                            const float* __restrict__ W1,
                            const float* __restrict__ W2,
                            const float* __restrict__ W3,
                            const float* __restrict__ W4) {
    int s = blockIdx.x * CTA_THREADS + threadIdx.x;
    const int E1 = NK1 * NJH * 32;
    const int E2 = E1 + NKH * NJH * 32;
    const int E3 = E2 + NKH * NJH * 32;
    const int E4 = E3 + NKH * NJO * 32;
    if (s >= E4) return;

    uint4* dst; int loc, nj, which;
    if (s < E1)      { dst = g_Wb1; loc = s;      nj = NJH; which = 1; }
    else if (s < E2) { dst = g_Wb2; loc = s - E1; nj = NJH; which = 2; }
    else if (s < E3) { dst = g_Wb3; loc = s - E2; nj = NJH; which = 3; }
    else             { dst = g_Wb4; loc = s - E3; nj = NJO; which = 4; }

    int lane = loc & 31;
    int j    = (loc >> 5) % nj;
    int ks   = loc / (nj * 32);
    int g = lane >> 2, t = lane & 3;
    int n  = 8 * j + g;
    int k0 = 16 * ks + 2 * t;

    float w0, w1, w8, w9;
    if (which == 1) {
        w0 = w_l1(cw, W1, k0,     n);
        w1 = w_l1(cw, W1, k0 + 1, n);
        w8 = w_l1(cw, W1, k0 + 8, n);
        w9 = w_l1(cw, W1, k0 + 9, n);
    } else if (which == 4) {
        w0 = (k0     < 200 && n < 10) ? W4[(k0)     * 10 + n] : 0.f;
        w1 = (k0 + 1 < 200 && n < 10) ? W4[(k0 + 1) * 10 + n] : 0.f;
        w8 = (k0 + 8 < 200 && n < 10) ? W4[(k0 + 8) * 10 + n] : 0.f;
        w9 = (k0 + 9 < 200 && n < 10) ? W4[(k0 + 9) * 10 + n] : 0.f;
    } else {
        const float* W = (which == 2) ? W2 : W3;
        w0 = (k0     < 200 && n < 200) ? W[(k0)     * 200 + n] : 0.f;
        w1 = (k0 + 1 < 200 && n < 200) ? W[(k0 + 1) * 200 + n] : 0.f;
        w8 = (k0 + 8 < 200 && n < 200) ? W[(k0 + 8) * 200 + n] : 0.f;
        w9 = (k0 + 9 < 200 && n < 200) ? W[(k0 + 9) * 200 + n] : 0.f;
    }

    uint32_t b0h, b0l, b1h, b1l;
    split_pack(w0, w1, b0h, b0l);
    split_pack(w8, w9, b1h, b1l);
    dst[loc] = make_uint4(b0h, b1h, b0l, b1l);
}

// ---------------------------------------------------------------------------
// main fused kernel (M = 64 rows per CTA -> 2 CTAs/SM)
// SMEM (floats):
//   [0,2560)        xs: 2 x [64][20] fp32 x-stage (stride 20)
//   [2560,9216)     ws: 2 x [832] uint4 weight stage
//   [9216,16128)    h_hi: [64][216] bf16 (as 64*108 u32, stride 108 u32)
//   [16128,23040)   h_lo: same
//   [23040,23680)   sb: biases b1[208] b2[208] b3[208] b4[16]
// ---------------------------------------------------------------------------
#define SMEM_BYTES 94720

__global__ void __launch_bounds__(CTA_THREADS, 2)
mlp_kernel(const float* __restrict__ x,
           const float* __restrict__ b1, const float* __restrict__ b2,
           const float* __restrict__ b3, const float* __restrict__ b4,
           float* __restrict__ out) {
    extern __shared__ float smf[];
    float*    xs = smf;                               // 2 x 1280 floats
    uint4*    ws = (uint4*)(smf + 2560);              // 2 x 832 uint4
    uint32_t* hh = (uint32_t*)(smf + 9216);           // 64*108 u32
    uint32_t* hl = (uint32_t*)(smf + 16128);
    float*    sb = smf + 23040;

    const int tid  = threadIdx.x;
    const int lane = tid & 31;
    const int warp = tid >> 5;
    const int g = lane >> 2, t = lane & 3;
    const int mq = warp >> 1;       // M-quarter 0..3 (16 rows each)
    const int nh = warp & 1;        // N-half
    const int r0 = blockIdx.x * 64;

    // biases (padded)
    if (tid < 208) {
        sb[tid]       = (tid < 200) ? b1[tid] : 0.f;
        sb[208 + tid] = (tid < 200) ? b2[tid] : 0.f;
        sb[416 + tid] = (tid < 200) ? b3[tid] : 0.f;
    }
    if (tid < 16) sb[624 + tid] = (tid < 10) ? b4[tid] : 0.f;

    float C[13][4];

    // --------------------- helper lambdas ---------------------
    auto stage_w = [&](const uint4* src, int count, int buf) {
        uint4* d = ws + buf * 832;
        for (int i = tid; i < count; i += CTA_THREADS) cp16(d + i, src + i);
    };
    auto stage_x = [&](int ks, int buf) {
        float* d = xs + buf * 1280;
        // 64 rows x 16 floats = 256 float4 segs, one per thread
        int row = tid >> 2, seg = tid & 3;
        cp16(d + row * 20 + seg * 4, x + (size_t)(r0 + row) * 784 + ks * 16 + seg * 4);
    };
    auto zeroC = [&]() {
        #pragma unroll
        for (int j = 0; j < 13; ++j)
            #pragma unroll
            for (int q = 0; q < 4; ++q) C[j][q] = 0.f;
    };
    auto store_h = [&](const float* bias) {
        int row = mq * 16 + g;
        #pragma unroll
        for (int j = 0; j < 13; ++j) {
            int J = 13 * nh + j;
            float2 bb = *(const float2*)(bias + 8 * J + 2 * t);
            float v0 = fmaxf(C[j][0] + bb.x, 0.f);
            float v1 = fmaxf(C[j][1] + bb.y, 0.f);
            float v2 = fmaxf(C[j][2] + bb.x, 0.f);
            float v3 = fmaxf(C[j][3] + bb.y, 0.f);
            uint32_t H, L;
            split_pack(v0, v1, H, L);
            hh[row * 108 + 4 * J + t] = H;
            hl[row * 108 + 4 * J + t] = L;
            split_pack(v2, v3, H, L);
            hh[(row + 8) * 108 + 4 * J + t] = H;
            hl[(row + 8) * 108 + 4 * J + t] = L;
        }
    };
    auto load_a_h = [&](int ks, uint32_t ah[4], uint32_t al[4]) {
        int base = (mq * 16 + g) * 108 + 8 * ks + t;
        ah[0] = hh[base];
        ah[1] = hh[base + 8 * 108];
        ah[2] = hh[base + 4];
        ah[3] = hh[base + 4 + 8 * 108];
        al[0] = hl[base];
        al[1] = hl[base + 8 * 108];
        al[2] = hl[base + 4];
        al[3] = hl[base + 4 + 8 * 108];
    };

    // =========================== Layer 1 (K=784) ===========================
    zeroC();
    stage_x(0, 0);
    stage_w(g_Wb1, 832, 0);
    CP_COMMIT;
    for (int ks = 0; ks < NK1; ++ks) {
        __syncthreads();                       // prior buf consumption done
        int cur = ks & 1, nb = cur ^ 1;
        if (ks + 1 < NK1) { stage_x(ks + 1, nb); stage_w(g_Wb1 + (ks + 1) * 832, 832, nb); }
        CP_COMMIT; CP_WAIT1;
        __syncthreads();                       // cur buffers visible

        uint32_t ah[4], al[4];
        {
            const float* xb = xs + cur * 1280 + (mq * 16 + g) * 20;
            float2 p0 = *(const float2*)(xb + 2 * t);
            float2 p1 = *(const float2*)(xb + 160 + 2 * t);        // row+8
            float2 p2 = *(const float2*)(xb + 2 * t + 8);          // k+8
            float2 p3 = *(const float2*)(xb + 160 + 2 * t + 8);
            split_pack(p0.x, p0.y, ah[0], al[0]);
            split_pack(p1.x, p1.y, ah[1], al[1]);
            split_pack(p2.x, p2.y, ah[2], al[2]);
            split_pack(p3.x, p3.y, ah[3], al[3]);
        }
        const uint4* wb = ws + cur * 832 + nh * 13 * 32 + lane;
        #pragma unroll
        for (int j = 0; j < 13; ++j) {
            uint4 w = wb[j * 32];
            mma_bf16(C[j], ah, w.x, w.y);   // hi*hi
            mma_bf16(C[j], al, w.x, w.y);   // lo*hi
            mma_bf16(C[j], ah, w.z, w.w);   // hi*lo
        }
    }
    __syncthreads();
    store_h(sb);
    __syncthreads();

    // ======================= Layers 2 & 3 (K=208) ==========================
    const uint4* Wmid[2] = { g_Wb2, g_Wb3 };
    for (int l = 0; l < 2; ++l) {
        zeroC();
        stage_w(Wmid[l], 832, 0);
        CP_COMMIT;
        for (int ks = 0; ks < NKH; ++ks) {
            __syncthreads();
            int cur = ks & 1, nb = cur ^ 1;
            if (ks + 1 < NKH) stage_w(Wmid[l] + (ks + 1) * 832, 832, nb);
            CP_COMMIT; CP_WAIT1;
            __syncthreads();

            uint32_t ah[4], al[4];
            load_a_h(ks, ah, al);
            const uint4* wb = ws + cur * 832 + nh * 13 * 32 + lane;
            #pragma unroll
            for (int j = 0; j < 13; ++j) {
                uint4 w = wb[j * 32];
                mma_bf16(C[j], ah, w.x, w.y);
                mma_bf16(C[j], al, w.x, w.y);
                mma_bf16(C[j], ah, w.z, w.w);
            }
        }
        __syncthreads();                 // all h reads done before overwrite
        store_h(sb + 208 * (l + 1));
        __syncthreads();
    }

    // =========================== Layer 4 (N=10) ============================
    float C4[4];
    #pragma unroll
    for (int q = 0; q < 4; ++q) C4[q] = 0.f;

    stage_w(g_Wb4, 64, 0);
    CP_COMMIT;
    for (int ks = 0; ks < NKH; ++ks) {
        __syncthreads();
        int cur = ks & 1, nb = cur ^ 1;
        if (ks + 1 < NKH) stage_w(g_Wb4 + (ks + 1) * 64, 64, nb);
        CP_COMMIT; CP_WAIT1;
        __syncthreads();

        uint32_t ah[4], al[4];
        load_a_h(ks, ah, al);
        uint4 w = ws[cur * 832 + nh * 32 + lane];
        mma_bf16(C4, ah, w.x, w.y);
        mma_bf16(C4, al, w.x, w.y);
        mma_bf16(C4, ah, w.z, w.w);
    }

    // output: cols 0..9 (tile nh*8 + 2t; guard padded cols)
    if (nh == 0 || t == 0) {
        int col = 8 * nh + 2 * t;
        float2 bb = *(const float2*)(sb + 624 + col);
        int rowg = r0 + mq * 16 + g;
        float2 o0 = { C4[0] + bb.x, C4[1] + bb.y };
        float2 o1 = { C4[2] + bb.x, C4[3] + bb.y };
        *(float2*)(out + (size_t)rowg * 10 + col)       = o0;
        *(float2*)(out + (size_t)(rowg + 8) * 10 + col) = o1;
    }
}

// ---------------------------------------------------------------------------
extern "C" void kernel_launch(void* const* d_in, const int* in_sizes, int n_in,
                              void* d_out, int out_size) {
    const float* x  = (const float*)d_in[0];
    const float* cw = (const float*)d_in[1];
    const float* W1 = (const float*)d_in[2];
    const float* b1 = (const float*)d_in[3];
    const float* W2 = (const float*)d_in[4];
    const float* b2 = (const float*)d_in[5];
    const float* W3 = (const float*)d_in[6];
    const float* b3 = (const float*)d_in[7];
    const float* W4 = (const float*)d_in[8];
    const float* b4 = (const float*)d_in[9];
    float* out = (float*)d_out;

    cudaFuncSetAttribute(mlp_kernel, cudaFuncAttributeMaxDynamicSharedMemorySize, SMEM_BYTES);

    prep_kernel<<<247, CTA_THREADS>>>(cw, W1, W2, W3, W4);
    mlp_kernel<<<1024, CTA_THREADS, SMEM_BYTES>>>(x, b1, b2, b3, b4, out);
}

// round 7
// speedup vs baseline: 1.3209x; 1.0729x over previous
#include <cuda_runtime.h>
#include <cuda_bf16.h>
#include <cstdint>

// ============================================================================
// DigitConvolutionalModel: conv folds into W1 -> pure 4-layer MLP
//   784 -> 200 -> 200 -> 200 -> 10, batch 65536, fp32 in/out.
// Legacy-tensor path (toolchain targets sm_100: no tcgen05).
//   bf16x3 split arithmetic (fp32-accurate), mma.sync.m16n8k16.
//   One CTA = 64 rows, 256 threads, 8 warps = 4 M-quarters(16 rows) x 2 N-halves.
//   3-deep cp.async ring, ONE __syncthreads per k-chunk (WAR ordered by ring
//   depth).  SMEM 113.2 KB -> 2 CTAs/SM.
//   Weights pre-folded + pre-split + fragment-linearized by a prep kernel.
// ============================================================================

#define CTA_THREADS 256

// padded dims: K1=784 (49 k-chunks), HID pad 208 (13 k-chunks, 26 n8-tiles),
// OUT pad 16 (2 n8-tiles)
#define NK1 49
#define NKH 13
#define NJH 26
#define NJO 2

// fragment-linear weight scratch (uint4 per (ks, j, lane)):
// {b0_hi, b1_hi, b0_lo, b1_lo}, each = 2 packed bf16 (low 16 bits = even k)
__device__ uint4 g_Wb1[NK1 * NJH * 32];   // 40768
__device__ uint4 g_Wb2[NKH * NJH * 32];   // 10816
__device__ uint4 g_Wb3[NKH * NJH * 32];   // 10816
__device__ uint4 g_Wb4[NKH * NJO * 32];   //   832

// ---------------------------------------------------------------------------
// helpers
// ---------------------------------------------------------------------------
__device__ __forceinline__ void split_pack(float x, float y, uint32_t& h, uint32_t& l) {
    __nv_bfloat16 hx = __float2bfloat16_rn(x);
    __nv_bfloat16 hy = __float2bfloat16_rn(y);
    float rx = x - __bfloat162float(hx);
    float ry = y - __bfloat162float(hy);
    __nv_bfloat162 H; H.x = hx; H.y = hy;
    __nv_bfloat162 L; L.x = __float2bfloat16_rn(rx); L.y = __float2bfloat16_rn(ry);
    h = *reinterpret_cast<uint32_t*>(&H);
    l = *reinterpret_cast<uint32_t*>(&L);
}

__device__ __forceinline__ void mma_bf16(float* c, const uint32_t* a,
                                         uint32_t b0, uint32_t b1) {
    asm volatile(
        "mma.sync.aligned.m16n8k16.row.col.f32.bf16.bf16.f32 "
        "{%0,%1,%2,%3},{%4,%5,%6,%7},{%8,%9},{%0,%1,%2,%3};"
        : "+f"(c[0]), "+f"(c[1]), "+f"(c[2]), "+f"(c[3])
        : "r"(a[0]), "r"(a[1]), "r"(a[2]), "r"(a[3]), "r"(b0), "r"(b1));
}

__device__ __forceinline__ void cp16(void* dst_smem, const void* src) {
    uint32_t d = (uint32_t)__cvta_generic_to_shared(dst_smem);
    asm volatile("cp.async.cg.shared.global [%0], [%1], 16;" :: "r"(d), "l"(src));
}
#define CP_COMMIT asm volatile("cp.async.commit_group;" ::: "memory")
#define CP_WAIT1  asm volatile("cp.async.wait_group 1;" ::: "memory")

// ---------------------------------------------------------------------------
// prep kernel: fold conv into W1eff, bf16 hi/lo split, fragment-linearize
// ---------------------------------------------------------------------------
__device__ __forceinline__ float w_l1(const float* cw, const float* W1, int k, int n) {
    if (n >= 200) return 0.f;
    int r = k / 28, c = k % 28;
    float s = 0.f;
    #pragma unroll
    for (int dy = 0; dy < 3; ++dy) {
        int i = r - dy;
        if (i < 0 || i > 25) continue;
        #pragma unroll
        for (int dx = 0; dx < 3; ++dx) {
            int j = c - dx;
            if (j < 0 || j > 25) continue;
            s += cw[dy * 3 + dx] * W1[(i * 26 + j) * 200 + n];
        }
    }
    return s;
}

__global__ void prep_kernel(const float* __restrict__ cw,
                            const float* __restrict__ W1,
                            const float* __restrict__ W2,
                            const float* __restrict__ W3,
                            const float* __restrict__ W4) {
    int s = blockIdx.x * CTA_THREADS + threadIdx.x;
    const int E1 = NK1 * NJH * 32;
    const int E2 = E1 + NKH * NJH * 32;
    const int E3 = E2 + NKH * NJH * 32;
    const int E4 = E3 + NKH * NJO * 32;
    if (s >= E4) return;

    uint4* dst; int loc, nj, which;
    if (s < E1)      { dst = g_Wb1; loc = s;      nj = NJH; which = 1; }
    else if (s < E2) { dst = g_Wb2; loc = s - E1; nj = NJH; which = 2; }
    else if (s < E3) { dst = g_Wb3; loc = s - E2; nj = NJH; which = 3; }
    else             { dst = g_Wb4; loc = s - E3; nj = NJO; which = 4; }

    int lane = loc & 31;
    int j    = (loc >> 5) % nj;
    int ks   = loc / (nj * 32);
    int g = lane >> 2, t = lane & 3;
    int n  = 8 * j + g;
    int k0 = 16 * ks + 2 * t;

    float w0, w1, w8, w9;
    if (which == 1) {
        w0 = w_l1(cw, W1, k0,     n);
        w1 = w_l1(cw, W1, k0 + 1, n);
        w8 = w_l1(cw, W1, k0 + 8, n);
        w9 = w_l1(cw, W1, k0 + 9, n);
    } else if (which == 4) {
        w0 = (k0     < 200 && n < 10) ? W4[(k0)     * 10 + n] : 0.f;
        w1 = (k0 + 1 < 200 && n < 10) ? W4[(k0 + 1) * 10 + n] : 0.f;
        w8 = (k0 + 8 < 200 && n < 10) ? W4[(k0 + 8) * 10 + n] : 0.f;
        w9 = (k0 + 9 < 200 && n < 10) ? W4[(k0 + 9) * 10 + n] : 0.f;
    } else {
        const float* W = (which == 2) ? W2 : W3;
        w0 = (k0     < 200 && n < 200) ? W[(k0)     * 200 + n] : 0.f;
        w1 = (k0 + 1 < 200 && n < 200) ? W[(k0 + 1) * 200 + n] : 0.f;
        w8 = (k0 + 8 < 200 && n < 200) ? W[(k0 + 8) * 200 + n] : 0.f;
        w9 = (k0 + 9 < 200 && n < 200) ? W[(k0 + 9) * 200 + n] : 0.f;
    }

    uint32_t b0h, b0l, b1h, b1l;
    split_pack(w0, w1, b0h, b0l);
    split_pack(w8, w9, b1h, b1l);
    dst[loc] = make_uint4(b0h, b1h, b0l, b1l);
}

// ---------------------------------------------------------------------------
// main fused kernel (M = 64 rows per CTA, 3-deep ring, 1 barrier/chunk)
// SMEM (floats):
//   [0,3840)        xs: 3 x [64][20] fp32 x-stage (stride 20)
//   [3840,13824)    ws: 3 x [832] uint4 weight stage
//   [13824,20736)   h_hi: [64][216] bf16 (as 64*108 u32, stride 108 u32)
//   [20736,27648)   h_lo: same
//   [27648,28288)   sb: biases b1[208] b2[208] b3[208] b4[16]
// ---------------------------------------------------------------------------
#define SMEM_BYTES 113152

__global__ void __launch_bounds__(CTA_THREADS, 2)
mlp_kernel(const float* __restrict__ x,
           const float* __restrict__ b1, const float* __restrict__ b2,
           const float* __restrict__ b3, const float* __restrict__ b4,
           float* __restrict__ out) {
    extern __shared__ float smf[];
    float*    xs = smf;                               // 3 x 1280 floats
    uint4*    ws = (uint4*)(smf + 3840);              // 3 x 832 uint4
    uint32_t* hh = (uint32_t*)(smf + 13824);          // 64*108 u32
    uint32_t* hl = (uint32_t*)(smf + 20736);
    float*    sb = smf + 27648;

    const int tid  = threadIdx.x;
    const int lane = tid & 31;
    const int warp = tid >> 5;
    const int g = lane >> 2, t = lane & 3;
    const int mq = warp >> 1;       // M-quarter 0..3 (16 rows each)
    const int nh = warp & 1;        // N-half
    const int r0 = blockIdx.x * 64;

    // biases (padded)
    if (tid < 208) {
        sb[tid]       = (tid < 200) ? b1[tid] : 0.f;
        sb[208 + tid] = (tid < 200) ? b2[tid] : 0.f;
        sb[416 + tid] = (tid < 200) ? b3[tid] : 0.f;
    }
    if (tid < 16) sb[624 + tid] = (tid < 10) ? b4[tid] : 0.f;

    float C[13][4];

    // --------------------- helper lambdas ---------------------
    auto stage_w = [&](const uint4* src, int count, int buf) {
        uint4* d = ws + buf * 832;
        for (int i = tid; i < count; i += CTA_THREADS) cp16(d + i, src + i);
    };
    auto stage_x = [&](int ks, int buf) {
        float* d = xs + buf * 1280;
        // 64 rows x 16 floats = 256 float4 segs, one per thread
        int row = tid >> 2, seg = tid & 3;
        cp16(d + row * 20 + seg * 4, x + (size_t)(r0 + row) * 784 + ks * 16 + seg * 4);
    };
    auto zeroC = [&]() {
        #pragma unroll
        for (int j = 0; j < 13; ++j)
            #pragma unroll
            for (int q = 0; q < 4; ++q) C[j][q] = 0.f;
    };
    auto store_h = [&](const float* bias) {
        int row = mq * 16 + g;
        #pragma unroll
        for (int j = 0; j < 13; ++j) {
            int J = 13 * nh + j;
            float2 bb = *(const float2*)(bias + 8 * J + 2 * t);
            float v0 = fmaxf(C[j][0] + bb.x, 0.f);
            float v1 = fmaxf(C[j][1] + bb.y, 0.f);
            float v2 = fmaxf(C[j][2] + bb.x, 0.f);
            float v3 = fmaxf(C[j][3] + bb.y, 0.f);
            uint32_t H, L;
            split_pack(v0, v1, H, L);
            hh[row * 108 + 4 * J + t] = H;
            hl[row * 108 + 4 * J + t] = L;
            split_pack(v2, v3, H, L);
            hh[(row + 8) * 108 + 4 * J + t] = H;
            hl[(row + 8) * 108 + 4 * J + t] = L;
        }
    };
    auto load_a_h = [&](int ks, uint32_t ah[4], uint32_t al[4]) {
        int base = (mq * 16 + g) * 108 + 8 * ks + t;
        ah[0] = hh[base];
        ah[1] = hh[base + 8 * 108];
        ah[2] = hh[base + 4];
        ah[3] = hh[base + 4 + 8 * 108];
        al[0] = hl[base];
        al[1] = hl[base + 8 * 108];
        al[2] = hl[base + 4];
        al[3] = hl[base + 4 + 8 * 108];
    };
    auto mma_wtile = [&](const uint4* wb) {
        // placeholder (unused) -- kept minimal
    };

    // =========================== Layer 1 (K=784) ===========================
    // Ring: one barrier per chunk. Iter ks: wait(G_ks done) -> barrier ->
    // stage G_{ks+2} -> commit -> consume chunk ks from buf cur.
    zeroC();
    stage_x(0, 0); stage_w(g_Wb1, 832, 0); CP_COMMIT;
    stage_x(1, 1); stage_w(g_Wb1 + 832, 832, 1); CP_COMMIT;
    {
        int cur = 0, st = 2;
        for (int ks = 0; ks < NK1; ++ks) {
            CP_WAIT1;                      // group ks complete (ks+1 pending)
            __syncthreads();               // visibility + WAR for buf st
            if (ks + 2 < NK1) { stage_x(ks + 2, st); stage_w(g_Wb1 + (ks + 2) * 832, 832, st); }
            CP_COMMIT;                     // commit every iter (may be empty)

            uint32_t ah[4], al[4];
            {
                const float* xb = xs + cur * 1280 + (mq * 16 + g) * 20;
                float2 p0 = *(const float2*)(xb + 2 * t);
                float2 p1 = *(const float2*)(xb + 160 + 2 * t);        // row+8
                float2 p2 = *(const float2*)(xb + 2 * t + 8);          // k+8
                float2 p3 = *(const float2*)(xb + 160 + 2 * t + 8);
                split_pack(p0.x, p0.y, ah[0], al[0]);
                split_pack(p1.x, p1.y, ah[1], al[1]);
                split_pack(p2.x, p2.y, ah[2], al[2]);
                split_pack(p3.x, p3.y, ah[3], al[3]);
            }
            const uint4* wb = ws + cur * 832 + nh * 13 * 32 + lane;
            #pragma unroll
            for (int j = 0; j < 13; ++j) {
                uint4 w = wb[j * 32];
                mma_bf16(C[j], ah, w.x, w.y);   // hi*hi
                mma_bf16(C[j], al, w.x, w.y);   // lo*hi
                mma_bf16(C[j], ah, w.z, w.w);   // hi*lo
            }
            if (++cur == 3) cur = 0;
            if (++st  == 3) st  = 0;
        }
    }
    __syncthreads();
    store_h(sb);
    __syncthreads();

    // ======================= Layers 2 & 3 (K=208) ==========================
    const uint4* Wmid[2] = { g_Wb2, g_Wb3 };
    for (int l = 0; l < 2; ++l) {
        zeroC();
        stage_w(Wmid[l], 832, 0); CP_COMMIT;
        stage_w(Wmid[l] + 832, 832, 1); CP_COMMIT;
        int cur = 0, st = 2;
        for (int ks = 0; ks < NKH; ++ks) {
            CP_WAIT1;
            __syncthreads();
            if (ks + 2 < NKH) stage_w(Wmid[l] + (ks + 2) * 832, 832, st);
            CP_COMMIT;

            uint32_t ah[4], al[4];
            load_a_h(ks, ah, al);
            const uint4* wb = ws + cur * 832 + nh * 13 * 32 + lane;
            #pragma unroll
            for (int j = 0; j < 13; ++j) {
                uint4 w = wb[j * 32];
                mma_bf16(C[j], ah, w.x, w.y);
                mma_bf16(C[j], al, w.x, w.y);
                mma_bf16(C[j], ah, w.z, w.w);
            }
            if (++cur == 3) cur = 0;
            if (++st  == 3) st  = 0;
        }
        __syncthreads();                 // all h reads done before overwrite
        store_h(sb + 208 * (l + 1));
        __syncthreads();
    }

    // =========================== Layer 4 (N=10) ============================
    float C4[4];
    #pragma unroll
    for (int q = 0; q < 4; ++q) C4[q] = 0.f;

    stage_w(g_Wb4, 64, 0); CP_COMMIT;
    stage_w(g_Wb4 + 64, 64, 1); CP_COMMIT;
    {
        int cur = 0, st = 2;
        for (int ks = 0; ks < NKH; ++ks) {
            CP_WAIT1;
            __syncthreads();
            if (ks + 2 < NKH) stage_w(g_Wb4 + (ks + 2) * 64, 64, st);
            CP_COMMIT;

            uint32_t ah[4], al[4];
            load_a_h(ks, ah, al);
            uint4 w = ws[cur * 832 + nh * 32 + lane];
            mma_bf16(C4, ah, w.x, w.y);
            mma_bf16(C4, al, w.x, w.y);
            mma_bf16(C4, ah, w.z, w.w);
            if (++cur == 3) cur = 0;
            if (++st  == 3) st  = 0;
        }
    }

    // output: cols 0..9 (tile nh*8 + 2t; guard padded cols)
    if (nh == 0 || t == 0) {
        int col = 8 * nh + 2 * t;
        float2 bb = *(const float2*)(sb + 624 + col);
        int rowg = r0 + mq * 16 + g;
        float2 o0 = { C4[0] + bb.x, C4[1] + bb.y };
        float2 o1 = { C4[2] + bb.x, C4[3] + bb.y };
        *(float2*)(out + (size_t)rowg * 10 + col)       = o0;
        *(float2*)(out + (size_t)(rowg + 8) * 10 + col) = o1;
    }
}

// ---------------------------------------------------------------------------
extern "C" void kernel_launch(void* const* d_in, const int* in_sizes, int n_in,
                              void* d_out, int out_size) {
    const float* x  = (const float*)d_in[0];
    const float* cw = (const float*)d_in[1];
    const float* W1 = (const float*)d_in[2];
    const float* b1 = (const float*)d_in[3];
    const float* W2 = (const float*)d_in[4];
    const float* b2 = (const float*)d_in[5];
    const float* W3 = (const float*)d_in[6];
    const float* b3 = (const float*)d_in[7];
    const float* W4 = (const float*)d_in[8];
    const float* b4 = (const float*)d_in[9];
    float* out = (float*)d_out;

    cudaFuncSetAttribute(mlp_kernel, cudaFuncAttributeMaxDynamicSharedMemorySize, SMEM_BYTES);

    prep_kernel<<<247, CTA_THREADS>>>(cw, W1, W2, W3, W4);
    mlp_kernel<<<1024, CTA_THREADS, SMEM_BYTES>>>(x, b1, b2, b3, b4, out);
}